// round 11
// baseline (speedup 1.0000x reference)
#include <cuda_runtime.h>
#include <cuda_fp16.h>
#include <cuda_pipeline.h>
#include <mma.h>
#include <math.h>

#define TOK   4096
#define DIMC  1024
#define MLPC  4096
#define NSEQ  512
#define HD    64
#define PART  256

#define F_BIAS  1
#define F_GELU  2
#define F_RES   4
#define F_OUTF  16
#define F_OUTH  32
#define F_FUSE  64

using namespace nvcuda;

/* static device scratch */
__device__ __half g_xn_h [TOK * DIMC];
__device__ __half g_qkv_h[TOK * 3 * DIMC];
__device__ __half g_ctx_h[TOK * DIMC];
__device__ float  g_x1   [TOK * DIMC];
__device__ __half g_h_h  [TOK * MLPC];
__device__ __half g_qkvw_h[DIMC * 3 * DIMC];
__device__ __half g_outw_h[DIMC * DIMC];
__device__ __half g_fc1w_h[DIMC * MLPC];
__device__ __half g_fc2w_h[MLPC * (DIMC - PART)];
__device__ __half g_expw_h[8 * MLPC * PART];

__device__ __forceinline__ float gelu_f(float v) {
    return 0.5f * v * (1.0f + erff(v * 0.70710678118654752f));
}

/* fused fp32 to fp16 conversion over five weight tensors */
__global__ void cvt5_k(const float* __restrict__ w0, __half* __restrict__ o0, int n0,
                       const float* __restrict__ w1, __half* __restrict__ o1, int n1,
                       const float* __restrict__ w2, __half* __restrict__ o2, int n2,
                       const float* __restrict__ w3, __half* __restrict__ o3, int n3,
                       const float* __restrict__ w4, __half* __restrict__ o4, int n4) {
    int i = blockIdx.x * blockDim.x + threadIdx.x;
    const float* in;
    __half* out;
    if (i < n0) {
        in = w0; out = o0;
    } else if (i < n0 + n1) {
        i -= n0; in = w1; out = o1;
    } else if (i < n0 + n1 + n2) {
        i -= n0 + n1; in = w2; out = o2;
    } else if (i < n0 + n1 + n2 + n3) {
        i -= n0 + n1 + n2; in = w3; out = o3;
    } else if (i < n0 + n1 + n2 + n3 + n4) {
        i -= n0 + n1 + n2 + n3; in = w4; out = o4;
    } else {
        return;
    }
    float4 v = reinterpret_cast<const float4*>(in)[i];
    reinterpret_cast<__half2*>(out)[i * 2 + 0] = __floats2half2_rn(v.x, v.y);
    reinterpret_cast<__half2*>(out)[i * 2 + 1] = __floats2half2_rn(v.z, v.w);
}

/* layernorm fp32 in, fp16 out */
__global__ void layernorm_h_k(const float* __restrict__ x,
                              const float* __restrict__ w,
                              const float* __restrict__ b,
                              __half* __restrict__ out) {
    int row = blockIdx.x;
    int t = threadIdx.x;
    float4 v = reinterpret_cast<const float4*>(x + (size_t)row * DIMC)[t];
    float s  = v.x + v.y + v.z + v.w;
    float sq = v.x * v.x + v.y * v.y + v.z * v.z + v.w * v.w;
    #pragma unroll
    for (int o = 16; o > 0; o >>= 1) {
        s  += __shfl_down_sync(0xffffffffu, s,  o);
        sq += __shfl_down_sync(0xffffffffu, sq, o);
    }
    __shared__ float ss[8];
    __shared__ float sq2[8];
    __shared__ float mean_s;
    __shared__ float rstd_s;
    int lane = t & 31;
    int wp = t >> 5;
    if (lane == 0) { ss[wp] = s; sq2[wp] = sq; }
    __syncthreads();
    if (t == 0) {
        float S = 0.f;
        float Q = 0.f;
        #pragma unroll
        for (int i = 0; i < 8; i++) { S += ss[i]; Q += sq2[i]; }
        float m = S * (1.0f / DIMC);
        mean_s = m;
        rstd_s = rsqrtf(Q * (1.0f / DIMC) - m * m + 1e-5f);
    }
    __syncthreads();
    float m = mean_s;
    float r = rstd_s;
    float4 wv = reinterpret_cast<const float4*>(w)[t];
    float4 bv = reinterpret_cast<const float4*>(b)[t];
    float o0 = (v.x - m) * r * wv.x + bv.x;
    float o1 = (v.y - m) * r * wv.y + bv.y;
    float o2 = (v.z - m) * r * wv.z + bv.z;
    float o3 = (v.w - m) * r * wv.w + bv.w;
    __half2* op = reinterpret_cast<__half2*>(out + (size_t)row * DIMC);
    op[t * 2 + 0] = __floats2half2_rn(o0, o1);
    op[t * 2 + 1] = __floats2half2_rn(o2, o3);
}

/*
 * Persistent fused attention: one CTA per (b,h). K and V live in smem for
 * the whole kernel; loop over 16 chunks of 32 query rows with
 * double-buffered Q prefetch. Per chunk: S = Q K^T (8 warps, 64-col
 * slices) -> softmax (writes fp32 attn + fp16 P aliased over S rows) ->
 * P @ V (2m x 4n warps, full K depth, dual accumulators) -> ctx fp16.
 */
__global__ __launch_bounds__(256, 1)
void attn_fused_k(const __half* __restrict__ qkv,
                  float* __restrict__ attn,
                  __half* __restrict__ ctx) {
    const int bh = blockIdx.x;
    const int b = bh >> 4;
    const int h = bh & 15;
    const int tid = threadIdx.x;
    const int warp = tid >> 5;
    const int lane = tid & 31;

    extern __shared__ __align__(16) char dyn[];
    __half* Ks = reinterpret_cast<__half*>(dyn);            /* 512 x 72 halves */
    __half* Vs = Ks + 512 * 72;                             /* 512 x 72 halves */
    float*  Ss = reinterpret_cast<float*>(Vs + 512 * 72);   /* 32 x 520 floats */
    __half* Qs = reinterpret_cast<__half*>(Ss + 32 * 520);  /* 2 x 32 x 72 halves */

    const __half* Qg = qkv + (long)b * NSEQ * 3 * DIMC + h * HD;
    const __half* Kg = Qg + DIMC;
    const __half* Vg = Qg + 2 * DIMC;

    /* load all of K, V and Q chunk 0 */
    #pragma unroll
    for (int q = 0; q < 16; q++) {
        const int idx = q * 256 + tid;
        const int row = idx >> 3;
        const int c = idx & 7;
        __pipeline_memcpy_async(&Ks[row * 72 + c * 8], Kg + (long)row * 3072 + c * 8, 16);
        __pipeline_memcpy_async(&Vs[row * 72 + c * 8], Vg + (long)row * 3072 + c * 8, 16);
    }
    {
        const int row = tid >> 3;
        const int c = tid & 7;
        __pipeline_memcpy_async(&Qs[row * 72 + c * 8], Qg + (long)row * 3072 + c * 8, 16);
    }
    __pipeline_commit();
    __pipeline_wait_prior(0);
    __syncthreads();

    for (int chunk = 0; chunk < 16; chunk++) {
        const int cur = chunk & 1;
        __half* Qc = Qs + cur * 32 * 72;

        /* prefetch next Q chunk into the other buffer */
        if (chunk + 1 < 16) {
            const int row = tid >> 3;
            const int c = tid & 7;
            __pipeline_memcpy_async(&Qs[(1 - cur) * 32 * 72 + row * 72 + c * 8],
                                    Qg + (long)((chunk + 1) * 32 + row) * 3072 + c * 8, 16);
            __pipeline_commit();
        }

        /* S = Q K^T : warp w covers cols [64w, 64w+64) */
        {
            wmma::fragment<wmma::accumulator, 16, 16, 16, float> sacc[2][4];
            #pragma unroll
            for (int mt = 0; mt < 2; mt++) {
                #pragma unroll
                for (int nt = 0; nt < 4; nt++) wmma::fill_fragment(sacc[mt][nt], 0.0f);
            }
            #pragma unroll
            for (int ks = 0; ks < 64; ks += 16) {
                wmma::fragment<wmma::matrix_a, 16, 16, 16, __half, wmma::row_major> af[2];
                #pragma unroll
                for (int mt = 0; mt < 2; mt++) {
                    wmma::load_matrix_sync(af[mt], &Qc[(mt * 16) * 72 + ks], 72);
                }
                wmma::fragment<wmma::matrix_b, 16, 16, 16, __half, wmma::col_major> bf[4];
                #pragma unroll
                for (int nt = 0; nt < 4; nt++) {
                    wmma::load_matrix_sync(bf[nt], &Ks[(warp * 64 + nt * 16) * 72 + ks], 72);
                }
                #pragma unroll
                for (int mt = 0; mt < 2; mt++) {
                    #pragma unroll
                    for (int nt = 0; nt < 4; nt++) {
                        wmma::mma_sync(sacc[mt][nt], af[mt], bf[nt], sacc[mt][nt]);
                    }
                }
            }
            #pragma unroll
            for (int mt = 0; mt < 2; mt++) {
                #pragma unroll
                for (int nt = 0; nt < 4; nt++) {
                    wmma::store_matrix_sync(&Ss[(mt * 16) * 520 + warp * 64 + nt * 16],
                                            sacc[mt][nt], 520, wmma::mem_row_major);
                }
            }
        }
        __syncthreads();

        /* softmax: warp w rows 4w..4w+3; write attn fp32, P fp16 aliased
           over the start of each fp32 S row (warp-private rows; the shfl
           reductions separate all reads from the aliased writes) */
        {
            float* attn_base = attn + ((long)bh * NSEQ + (long)chunk * 32) * NSEQ;
            #pragma unroll
            for (int rr = 0; rr < 4; rr++) {
                const int row = warp * 4 + rr;
                float v[16];
                float mx = -1e30f;
                #pragma unroll
                for (int j = 0; j < 16; j++) {
                    v[j] = Ss[row * 520 + lane + 32 * j] * 0.03125f;
                    mx = fmaxf(mx, v[j]);
                }
                #pragma unroll
                for (int o = 16; o > 0; o >>= 1) mx = fmaxf(mx, __shfl_xor_sync(0xffffffffu, mx, o));
                float sum = 0.f;
                #pragma unroll
                for (int j = 0; j < 16; j++) {
                    v[j] = expf(v[j] - mx);
                    sum += v[j];
                }
                #pragma unroll
                for (int o = 16; o > 0; o >>= 1) sum += __shfl_xor_sync(0xffffffffu, sum, o);
                const float inv = 1.0f / sum;
                __half* Pr = reinterpret_cast<__half*>(Ss + (size_t)row * 520);
                #pragma unroll
                for (int j = 0; j < 16; j++) {
                    const float e = v[j] * inv;
                    attn_base[(long)row * NSEQ + lane + 32 * j] = e;
                    Pr[lane + 32 * j] = __float2half(e);
                }
            }
        }
        __syncthreads();

        /* P @ V : warp (wm, wn), wm = warp&1, wn = warp>>1, computes the
           16x16 output tile at rows wm*16, cols wn*16, full K depth,
           two independent accumulator chains over even/odd 16-K slices */
        {
            const int wm = warp & 1;
            const int wn = warp >> 1;
            wmma::fragment<wmma::accumulator, 16, 16, 16, float> oacc0;
            wmma::fragment<wmma::accumulator, 16, 16, 16, float> oacc1;
            wmma::fill_fragment(oacc0, 0.0f);
            wmma::fill_fragment(oacc1, 0.0f);
            const __half* Pbase = reinterpret_cast<const __half*>(Ss) + (wm * 16) * 1040;
            #pragma unroll
            for (int ks = 0; ks < 512; ks += 32) {
                wmma::fragment<wmma::matrix_a, 16, 16, 16, __half, wmma::row_major> af0;
                wmma::fragment<wmma::matrix_a, 16, 16, 16, __half, wmma::row_major> af1;
                wmma::load_matrix_sync(af0, Pbase + ks, 1040);
                wmma::load_matrix_sync(af1, Pbase + ks + 16, 1040);
                wmma::fragment<wmma::matrix_b, 16, 16, 16, __half, wmma::row_major> bf0;
                wmma::fragment<wmma::matrix_b, 16, 16, 16, __half, wmma::row_major> bf1;
                wmma::load_matrix_sync(bf0, &Vs[ks * 72 + wn * 16], 72);
                wmma::load_matrix_sync(bf1, &Vs[(ks + 16) * 72 + wn * 16], 72);
                wmma::mma_sync(oacc0, af0, bf0, oacc0);
                wmma::mma_sync(oacc1, af1, bf1, oacc1);
            }
            #pragma unroll
            for (int e = 0; e < oacc0.num_elements; e++) oacc0.x[e] += oacc1.x[e];
            __syncthreads();
            float* stage = Ss;
            wmma::store_matrix_sync(&stage[(wm * 16) * 72 + wn * 16], oacc0, 72,
                                    wmma::mem_row_major);
        }
        __syncthreads();

        /* ctx write: fp32 stage -> fp16 */
        {
            const int r = tid >> 3;
            const int c0 = (tid & 7) * 8;
            float a8[8];
            #pragma unroll
            for (int j = 0; j < 8; j++) a8[j] = Ss[r * 72 + c0 + j];
            __half2 hv[4];
            #pragma unroll
            for (int j = 0; j < 4; j++) hv[j] = __floats2half2_rn(a8[2 * j], a8[2 * j + 1]);
            __half* cp = ctx + (long)b * NSEQ * DIMC + (long)(chunk * 32 + r) * DIMC + h * 64 + c0;
            *reinterpret_cast<float4*>(cp) = *reinterpret_cast<float4*>(hv);
        }
        __syncthreads();
        if (chunk + 1 < 16) {
            __pipeline_wait_prior(0);
        }
    }
}

/* one pipeline stage load: A tile 128x64, B tile 64xBN.
   Bp is pre-offset to the block's column start. */
template<int BN>
__device__ __forceinline__ void load_stage(const __half* A, int lda,
                                           const __half* Bp, long ldbv,
                                           int brow, int k0,
                                           __half* As, __half* Bs, int tid) {
    const int AP  = 72;
    const int BPN = BN + 8;
    const int lr = tid >> 1;
    const int lc = (tid & 1) * 32;
    const __half* ga = A + (long)(brow + lr) * lda + k0 + lc;
    #pragma unroll
    for (int j = 0; j < 4; j++) {
        __pipeline_memcpy_async(&As[lr * AP + lc + j * 8], ga + j * 8, 16);
    }
    const int CH = BN / 8;
    #pragma unroll
    for (int q = 0; q < (64 * CH + 255) / 256; q++) {
        const int idx = tid + q * 256;
        if (idx < 64 * CH) {
            const int r = idx / CH;
            const int c = idx % CH;
            __pipeline_memcpy_async(&Bs[r * BPN + c * 8],
                                    Bp + (long)(k0 + r) * ldbv + c * 8, 16);
        }
    }
}

/*
 * WMMA tensor-core GEMM (NN). Block tile 128 x BN, K-step 64, 3-stage
 * cp.async pipeline. 8 warps as 4(m) x 2(n). F_FUSE: column blocks at or
 * beyond DIMC-PART read the per-batch expert weight B2/bias2 instead.
 */
template<int BN, int FLAGS>
__global__ __launch_bounds__(256, 2)
void hgemm(const __half* __restrict__ A, int lda,
           const __half* __restrict__ B, int ldb,
           float* __restrict__ Cf, __half* __restrict__ Ch, int ldc,
           int K,
           const float* __restrict__ bias,
           const float* __restrict__ res, int ldr,
           const int* __restrict__ indices, long wstride, int bstride,
           const __half* __restrict__ B2, int ldb2,
           const float* __restrict__ bias2)
{
    const int brow = blockIdx.y * 128;
    const int bcol = blockIdx.x * BN;

    const __half* Bp = B + bcol;
    const float* biasp = (FLAGS & F_BIAS) ? (bias + bcol) : bias;
    long ldbv = ldb;
    if ((FLAGS & F_FUSE) && bcol >= (DIMC - PART)) {
        const int idx = indices[brow >> 9];
        Bp    = B2 + (long)idx * wstride + (bcol - (DIMC - PART));
        biasp = bias2 + (long)idx * bstride + (bcol - (DIMC - PART));
        ldbv  = ldb2;
    }

    constexpr int AP  = 72;
    constexpr int BPN = BN + 8;
    constexpr int ASZ = 128 * AP;
    constexpr int BSZ = 64 * BPN;

    extern __shared__ __align__(16) char dyn[];
    __half* As = reinterpret_cast<__half*>(dyn);
    __half* Bs = As + 3 * ASZ;

    const int tid  = threadIdx.x;
    const int warp = tid >> 5;
    const int lane = tid & 31;
    const int wm = warp & 3;
    const int wn = warp >> 2;
    constexpr int NTF = BN / 32;

    wmma::fragment<wmma::accumulator, 16, 16, 16, float> acc[2][NTF];
    #pragma unroll
    for (int i = 0; i < 2; i++) {
        #pragma unroll
        for (int j = 0; j < NTF; j++) wmma::fill_fragment(acc[i][j], 0.0f);
    }

    const int iters = K >> 6;

    load_stage<BN>(A, lda, Bp, ldbv, brow, 0, As, Bs, tid);
    __pipeline_commit();
    if (iters > 1) {
        load_stage<BN>(A, lda, Bp, ldbv, brow, 64, As + ASZ, Bs + BSZ, tid);
        __pipeline_commit();
    }

    for (int it = 0; it < iters; ++it) {
        if (it + 1 < iters) {
            __pipeline_wait_prior(1);
        } else {
            __pipeline_wait_prior(0);
        }
        __syncthreads();
        if (it + 2 < iters) {
            const int ns = (it + 2) % 3;
            load_stage<BN>(A, lda, Bp, ldbv, brow, (it + 2) * 64,
                           As + ns * ASZ, Bs + ns * BSZ, tid);
            __pipeline_commit();
        }
        const int slot = it % 3;

        #pragma unroll
        for (int ks = 0; ks < 64; ks += 16) {
            wmma::fragment<wmma::matrix_a, 16, 16, 16, __half, wmma::row_major> af[2];
            #pragma unroll
            for (int mt = 0; mt < 2; mt++) {
                const __half* ap = &As[slot * ASZ + (wm * 32 + mt * 16) * AP + ks];
                wmma::load_matrix_sync(af[mt], ap, AP);
            }
            wmma::fragment<wmma::matrix_b, 16, 16, 16, __half, wmma::row_major> bf[NTF];
            #pragma unroll
            for (int nt = 0; nt < NTF; nt++) {
                const __half* bp = &Bs[slot * BSZ + ks * BPN + wn * (BN / 2) + nt * 16];
                wmma::load_matrix_sync(bf[nt], bp, BPN);
            }
            #pragma unroll
            for (int mt = 0; mt < 2; mt++) {
                #pragma unroll
                for (int nt = 0; nt < NTF; nt++) {
                    wmma::mma_sync(acc[mt][nt], af[mt], bf[nt], acc[mt][nt]);
                }
            }
        }
    }

    __syncthreads();

    /* epilogue: stage each 16x16 accumulator through smem */
    float* stage = reinterpret_cast<float*>(dyn) + warp * 16 * 20;
    const int er = lane >> 1;
    const int ec = (lane & 1) * 8;
    #pragma unroll
    for (int mt = 0; mt < 2; mt++) {
        #pragma unroll
        for (int nt = 0; nt < NTF; nt++) {
            wmma::store_matrix_sync(stage, acc[mt][nt], 20, wmma::mem_row_major);
            __syncwarp();
            const int row = brow + wm * 32 + mt * 16 + er;
            const int lcol = wn * (BN / 2) + nt * 16 + ec;
            const int col = bcol + lcol;
            float v[8];
            #pragma unroll
            for (int j = 0; j < 8; j++) v[j] = stage[er * 20 + ec + j];
            if (FLAGS & F_BIAS) {
                #pragma unroll
                for (int j = 0; j < 8; j++) v[j] += biasp[lcol + j];
            }
            if (FLAGS & F_GELU) {
                #pragma unroll
                for (int j = 0; j < 8; j++) v[j] = gelu_f(v[j]);
            }
            if (FLAGS & F_RES) {
                #pragma unroll
                for (int j = 0; j < 8; j++) v[j] += res[(long)row * ldr + col + j];
            }
            const long off = (long)row * ldc + col;
            if (FLAGS & F_OUTF) {
                float4 f0;
                f0.x = v[0]; f0.y = v[1]; f0.z = v[2]; f0.w = v[3];
                float4 f1;
                f1.x = v[4]; f1.y = v[5]; f1.z = v[6]; f1.w = v[7];
                *reinterpret_cast<float4*>(&Cf[off]) = f0;
                *reinterpret_cast<float4*>(&Cf[off + 4]) = f1;
            }
            if (FLAGS & F_OUTH) {
                __half2* hp = reinterpret_cast<__half2*>(&Ch[off]);
                hp[0] = __floats2half2_rn(v[0], v[1]);
                hp[1] = __floats2half2_rn(v[2], v[3]);
                hp[2] = __floats2half2_rn(v[4], v[5]);
                hp[3] = __floats2half2_rn(v[6], v[7]);
            }
            __syncwarp();
        }
    }
}

#define SMEM_NN128 (3 * (128 * 72 + 64 * 136) * 2)
#define SMEM_ATTN  223232

extern "C" void kernel_launch(void* const* d_in, const int* in_sizes, int n_in,
                              void* d_out, int out_size) {
    const float* x       = (const float*)d_in[0];
    const int*   indices = (const int*)  d_in[1];
    const float* ln1_w   = (const float*)d_in[2];
    const float* ln1_b   = (const float*)d_in[3];
    const float* qkv_w   = (const float*)d_in[4];
    const float* qkv_b   = (const float*)d_in[5];
    const float* out_w   = (const float*)d_in[6];
    const float* out_b   = (const float*)d_in[7];
    const float* ln2_w   = (const float*)d_in[8];
    const float* ln2_b   = (const float*)d_in[9];
    const float* fc1_w   = (const float*)d_in[10];
    const float* fc1_b   = (const float*)d_in[11];
    const float* fc2_w   = (const float*)d_in[12];
    const float* fc2_b   = (const float*)d_in[13];
    const float* exp_w   = (const float*)d_in[14];
    const float* exp_b   = (const float*)d_in[15];

    float* out_final = (float*)d_out;
    float* attn      = out_final + (size_t)TOK * DIMC;

    void* p;
    cudaGetSymbolAddress(&p, g_xn_h);
    __half* xn_h = (__half*)p;
    cudaGetSymbolAddress(&p, g_qkv_h);
    __half* qkv_h = (__half*)p;
    cudaGetSymbolAddress(&p, g_ctx_h);
    __half* ctx_h = (__half*)p;
    cudaGetSymbolAddress(&p, g_x1);
    float* x1 = (float*)p;
    cudaGetSymbolAddress(&p, g_h_h);
    __half* h_h = (__half*)p;
    cudaGetSymbolAddress(&p, g_qkvw_h);
    __half* qkvw_h = (__half*)p;
    cudaGetSymbolAddress(&p, g_outw_h);
    __half* outw_h = (__half*)p;
    cudaGetSymbolAddress(&p, g_fc1w_h);
    __half* fc1w_h = (__half*)p;
    cudaGetSymbolAddress(&p, g_fc2w_h);
    __half* fc2w_h = (__half*)p;
    cudaGetSymbolAddress(&p, g_expw_h);
    __half* expw_h = (__half*)p;

    cudaFuncSetAttribute(hgemm<128, F_BIAS | F_OUTH>,
                         cudaFuncAttributeMaxDynamicSharedMemorySize, SMEM_NN128);
    cudaFuncSetAttribute(hgemm<128, F_BIAS | F_RES | F_OUTF>,
                         cudaFuncAttributeMaxDynamicSharedMemorySize, SMEM_NN128);
    cudaFuncSetAttribute(hgemm<128, F_BIAS | F_GELU | F_OUTH>,
                         cudaFuncAttributeMaxDynamicSharedMemorySize, SMEM_NN128);
    cudaFuncSetAttribute(hgemm<128, F_BIAS | F_RES | F_OUTF | F_FUSE>,
                         cudaFuncAttributeMaxDynamicSharedMemorySize, SMEM_NN128);
    cudaFuncSetAttribute(attn_fused_k,
                         cudaFuncAttributeMaxDynamicSharedMemorySize, SMEM_ATTN);

    const int n0 = DIMC * 3 * DIMC / 4;
    const int n1 = DIMC * DIMC / 4;
    const int n2 = DIMC * MLPC / 4;
    const int n3 = MLPC * (DIMC - PART) / 4;
    const int n4 = 8 * MLPC * PART / 4;
    const int ntot = n0 + n1 + n2 + n3 + n4;
    cvt5_k<<<(ntot + 255) / 256, 256>>>(qkv_w, qkvw_h, n0,
                                        out_w, outw_h, n1,
                                        fc1_w, fc1w_h, n2,
                                        fc2_w, fc2w_h, n3,
                                        exp_w, expw_h, n4);

    layernorm_h_k<<<TOK, 256>>>(x, ln1_w, ln1_b, xn_h);

    hgemm<128, F_BIAS | F_OUTH><<<dim3(24, 32), 256, SMEM_NN128>>>(
        xn_h, DIMC, qkvw_h, 3 * DIMC, nullptr, qkv_h, 3 * DIMC, DIMC,
        qkv_b, nullptr, 0, nullptr, 0, 0, nullptr, 0, nullptr);

    attn_fused_k<<<dim3(128), 256, SMEM_ATTN>>>(qkv_h, attn, ctx_h);

    hgemm<128, F_BIAS | F_RES | F_OUTF><<<dim3(8, 32), 256, SMEM_NN128>>>(
        ctx_h, DIMC, outw_h, DIMC, x1, nullptr, DIMC, DIMC,
        out_b, x, DIMC, nullptr, 0, 0, nullptr, 0, nullptr);

    layernorm_h_k<<<TOK, 256>>>(x1, ln2_w, ln2_b, xn_h);

    hgemm<128, F_BIAS | F_GELU | F_OUTH><<<dim3(32, 32), 256, SMEM_NN128>>>(
        xn_h, DIMC, fc1w_h, MLPC, nullptr, h_h, MLPC, DIMC,
        fc1_b, nullptr, 0, nullptr, 0, 0, nullptr, 0, nullptr);

    hgemm<128, F_BIAS | F_RES | F_OUTF | F_FUSE><<<dim3(8, 32), 256, SMEM_NN128>>>(
        h_h, MLPC, fc2w_h, DIMC - PART, out_final, nullptr, DIMC, MLPC,
        fc2_b, x1, DIMC,
        indices, (long)MLPC * PART, PART,
        expw_h, PART, exp_b);
}

// round 12
// speedup vs baseline: 1.0580x; 1.0580x over previous
#include <cuda_runtime.h>
#include <cuda_fp16.h>
#include <cuda_pipeline.h>
#include <mma.h>
#include <math.h>

#define TOK   4096
#define DIMC  1024
#define MLPC  4096
#define NSEQ  512
#define HD    64
#define PART  256

#define F_BIAS  1
#define F_GELU  2
#define F_RES   4
#define F_OUTF  16
#define F_OUTH  32
#define F_FUSE  64

using namespace nvcuda;

/* static device scratch */
__device__ __half g_xn_h [TOK * DIMC];
__device__ __half g_qkv_h[TOK * 3 * DIMC];
__device__ __half g_ctx_h[TOK * DIMC];
__device__ float  g_x1   [TOK * DIMC];
__device__ __half g_h_h  [TOK * MLPC];
__device__ __half g_qkvw_h[DIMC * 3 * DIMC];
__device__ __half g_outw_h[DIMC * DIMC];
__device__ __half g_fc1w_h[DIMC * MLPC];
__device__ __half g_fc2w_h[MLPC * (DIMC - PART)];
__device__ __half g_expw_h[8 * MLPC * PART];

__device__ __forceinline__ float gelu_f(float v) {
    return 0.5f * v * (1.0f + erff(v * 0.70710678118654752f));
}

/* fused fp32 to fp16 conversion over five weight tensors */
__global__ void cvt5_k(const float* __restrict__ w0, __half* __restrict__ o0, int n0,
                       const float* __restrict__ w1, __half* __restrict__ o1, int n1,
                       const float* __restrict__ w2, __half* __restrict__ o2, int n2,
                       const float* __restrict__ w3, __half* __restrict__ o3, int n3,
                       const float* __restrict__ w4, __half* __restrict__ o4, int n4) {
    int i = blockIdx.x * blockDim.x + threadIdx.x;
    const float* in;
    __half* out;
    if (i < n0) {
        in = w0; out = o0;
    } else if (i < n0 + n1) {
        i -= n0; in = w1; out = o1;
    } else if (i < n0 + n1 + n2) {
        i -= n0 + n1; in = w2; out = o2;
    } else if (i < n0 + n1 + n2 + n3) {
        i -= n0 + n1 + n2; in = w3; out = o3;
    } else if (i < n0 + n1 + n2 + n3 + n4) {
        i -= n0 + n1 + n2 + n3; in = w4; out = o4;
    } else {
        return;
    }
    float4 v = reinterpret_cast<const float4*>(in)[i];
    reinterpret_cast<__half2*>(out)[i * 2 + 0] = __floats2half2_rn(v.x, v.y);
    reinterpret_cast<__half2*>(out)[i * 2 + 1] = __floats2half2_rn(v.z, v.w);
}

/* layernorm fp32 in, fp16 out */
__global__ void layernorm_h_k(const float* __restrict__ x,
                              const float* __restrict__ w,
                              const float* __restrict__ b,
                              __half* __restrict__ out) {
    int row = blockIdx.x;
    int t = threadIdx.x;
    float4 v = reinterpret_cast<const float4*>(x + (size_t)row * DIMC)[t];
    float s  = v.x + v.y + v.z + v.w;
    float sq = v.x * v.x + v.y * v.y + v.z * v.z + v.w * v.w;
    #pragma unroll
    for (int o = 16; o > 0; o >>= 1) {
        s  += __shfl_down_sync(0xffffffffu, s,  o);
        sq += __shfl_down_sync(0xffffffffu, sq, o);
    }
    __shared__ float ss[8];
    __shared__ float sq2[8];
    __shared__ float mean_s;
    __shared__ float rstd_s;
    int lane = t & 31;
    int wp = t >> 5;
    if (lane == 0) { ss[wp] = s; sq2[wp] = sq; }
    __syncthreads();
    if (t == 0) {
        float S = 0.f;
        float Q = 0.f;
        #pragma unroll
        for (int i = 0; i < 8; i++) { S += ss[i]; Q += sq2[i]; }
        float m = S * (1.0f / DIMC);
        mean_s = m;
        rstd_s = rsqrtf(Q * (1.0f / DIMC) - m * m + 1e-5f);
    }
    __syncthreads();
    float m = mean_s;
    float r = rstd_s;
    float4 wv = reinterpret_cast<const float4*>(w)[t];
    float4 bv = reinterpret_cast<const float4*>(b)[t];
    float o0 = (v.x - m) * r * wv.x + bv.x;
    float o1 = (v.y - m) * r * wv.y + bv.y;
    float o2 = (v.z - m) * r * wv.z + bv.z;
    float o3 = (v.w - m) * r * wv.w + bv.w;
    __half2* op = reinterpret_cast<__half2*>(out + (size_t)row * DIMC);
    op[t * 2 + 0] = __floats2half2_rn(o0, o1);
    op[t * 2 + 1] = __floats2half2_rn(o2, o3);
}

/*
 * Persistent fused attention: one CTA per (b,h). K and V live in smem for
 * the whole kernel; loop over 16 chunks of 32 query rows with
 * double-buffered Q prefetch. Per chunk: S = Q K^T (8 warps, 64-col
 * slices) -> softmax (writes fp32 attn + fp16 P aliased over S rows) ->
 * P @ V (2m x 4n warps, full K depth) -> ctx fp16.
 */
__global__ __launch_bounds__(256, 1)
void attn_fused_k(const __half* __restrict__ qkv,
                  float* __restrict__ attn,
                  __half* __restrict__ ctx) {
    const int bh = blockIdx.x;
    const int b = bh >> 4;
    const int h = bh & 15;
    const int tid = threadIdx.x;
    const int warp = tid >> 5;
    const int lane = tid & 31;

    extern __shared__ __align__(16) char dyn[];
    __half* Ks = reinterpret_cast<__half*>(dyn);            /* 512 x 72 halves */
    __half* Vs = Ks + 512 * 72;                             /* 512 x 72 halves */
    float*  Ss = reinterpret_cast<float*>(Vs + 512 * 72);   /* 32 x 520 floats */
    __half* Qs = reinterpret_cast<__half*>(Ss + 32 * 520);  /* 2 x 32 x 72 halves */

    const __half* Qg = qkv + (long)b * NSEQ * 3 * DIMC + h * HD;
    const __half* Kg = Qg + DIMC;
    const __half* Vg = Qg + 2 * DIMC;

    /* load all of K, V and Q chunk 0 */
    #pragma unroll
    for (int q = 0; q < 16; q++) {
        const int idx = q * 256 + tid;
        const int row = idx >> 3;
        const int c = idx & 7;
        __pipeline_memcpy_async(&Ks[row * 72 + c * 8], Kg + (long)row * 3072 + c * 8, 16);
        __pipeline_memcpy_async(&Vs[row * 72 + c * 8], Vg + (long)row * 3072 + c * 8, 16);
    }
    {
        const int row = tid >> 3;
        const int c = tid & 7;
        __pipeline_memcpy_async(&Qs[row * 72 + c * 8], Qg + (long)row * 3072 + c * 8, 16);
    }
    __pipeline_commit();
    __pipeline_wait_prior(0);
    __syncthreads();

    for (int chunk = 0; chunk < 16; chunk++) {
        const int cur = chunk & 1;
        __half* Qc = Qs + cur * 32 * 72;

        /* prefetch next Q chunk into the other buffer */
        if (chunk + 1 < 16) {
            const int row = tid >> 3;
            const int c = tid & 7;
            __pipeline_memcpy_async(&Qs[(1 - cur) * 32 * 72 + row * 72 + c * 8],
                                    Qg + (long)((chunk + 1) * 32 + row) * 3072 + c * 8, 16);
            __pipeline_commit();
        }

        /* S = Q K^T : warp w covers cols [64w, 64w+64) */
        {
            wmma::fragment<wmma::accumulator, 16, 16, 16, float> sacc[2][4];
            #pragma unroll
            for (int mt = 0; mt < 2; mt++) {
                #pragma unroll
                for (int nt = 0; nt < 4; nt++) wmma::fill_fragment(sacc[mt][nt], 0.0f);
            }
            #pragma unroll
            for (int ks = 0; ks < 64; ks += 16) {
                wmma::fragment<wmma::matrix_a, 16, 16, 16, __half, wmma::row_major> af[2];
                #pragma unroll
                for (int mt = 0; mt < 2; mt++) {
                    wmma::load_matrix_sync(af[mt], &Qc[(mt * 16) * 72 + ks], 72);
                }
                wmma::fragment<wmma::matrix_b, 16, 16, 16, __half, wmma::col_major> bf[4];
                #pragma unroll
                for (int nt = 0; nt < 4; nt++) {
                    wmma::load_matrix_sync(bf[nt], &Ks[(warp * 64 + nt * 16) * 72 + ks], 72);
                }
                #pragma unroll
                for (int mt = 0; mt < 2; mt++) {
                    #pragma unroll
                    for (int nt = 0; nt < 4; nt++) {
                        wmma::mma_sync(sacc[mt][nt], af[mt], bf[nt], sacc[mt][nt]);
                    }
                }
            }
            #pragma unroll
            for (int mt = 0; mt < 2; mt++) {
                #pragma unroll
                for (int nt = 0; nt < 4; nt++) {
                    wmma::store_matrix_sync(&Ss[(mt * 16) * 520 + warp * 64 + nt * 16],
                                            sacc[mt][nt], 520, wmma::mem_row_major);
                }
            }
        }
        __syncthreads();

        /* softmax: warp w rows 4w..4w+3; write attn fp32, P fp16 aliased
           over the start of each fp32 S row (warp-private rows; the shfl
           reductions separate all reads from the aliased writes) */
        {
            float* attn_base = attn + ((long)bh * NSEQ + (long)chunk * 32) * NSEQ;
            #pragma unroll
            for (int rr = 0; rr < 4; rr++) {
                const int row = warp * 4 + rr;
                float v[16];
                float mx = -1e30f;
                #pragma unroll
                for (int j = 0; j < 16; j++) {
                    v[j] = Ss[row * 520 + lane + 32 * j] * 0.03125f;
                    mx = fmaxf(mx, v[j]);
                }
                #pragma unroll
                for (int o = 16; o > 0; o >>= 1) mx = fmaxf(mx, __shfl_xor_sync(0xffffffffu, mx, o));
                float sum = 0.f;
                #pragma unroll
                for (int j = 0; j < 16; j++) {
                    v[j] = expf(v[j] - mx);
                    sum += v[j];
                }
                #pragma unroll
                for (int o = 16; o > 0; o >>= 1) sum += __shfl_xor_sync(0xffffffffu, sum, o);
                const float inv = 1.0f / sum;
                __half* Pr = reinterpret_cast<__half*>(Ss + (size_t)row * 520);
                #pragma unroll
                for (int j = 0; j < 16; j++) {
                    const float e = v[j] * inv;
                    attn_base[(long)row * NSEQ + lane + 32 * j] = e;
                    Pr[lane + 32 * j] = __float2half(e);
                }
            }
        }
        __syncthreads();

        /* P @ V : warp (wm, wn) with wm = warp&1, wn = warp>>1 computes the
           16x16 output tile at rows wm*16, cols wn*16, full K depth */
        {
            const int wm = warp & 1;
            const int wn = warp >> 1;
            wmma::fragment<wmma::accumulator, 16, 16, 16, float> oacc;
            wmma::fill_fragment(oacc, 0.0f);
            const __half* Pbase = reinterpret_cast<const __half*>(Ss) + (wm * 16) * 1040;
            #pragma unroll
            for (int ks = 0; ks < 512; ks += 16) {
                wmma::fragment<wmma::matrix_a, 16, 16, 16, __half, wmma::row_major> af;
                wmma::load_matrix_sync(af, Pbase + ks, 1040);
                wmma::fragment<wmma::matrix_b, 16, 16, 16, __half, wmma::row_major> bf;
                wmma::load_matrix_sync(bf, &Vs[ks * 72 + wn * 16], 72);
                wmma::mma_sync(oacc, af, bf, oacc);
            }
            __syncthreads();
            float* stage = Ss;
            wmma::store_matrix_sync(&stage[(wm * 16) * 72 + wn * 16], oacc, 72,
                                    wmma::mem_row_major);
        }
        __syncthreads();

        /* ctx write: fp32 stage -> fp16 */
        {
            const int r = tid >> 3;
            const int c0 = (tid & 7) * 8;
            float a8[8];
            #pragma unroll
            for (int j = 0; j < 8; j++) a8[j] = Ss[r * 72 + c0 + j];
            __half2 hv[4];
            #pragma unroll
            for (int j = 0; j < 4; j++) hv[j] = __floats2half2_rn(a8[2 * j], a8[2 * j + 1]);
            __half* cp = ctx + (long)b * NSEQ * DIMC + (long)(chunk * 32 + r) * DIMC + h * 64 + c0;
            *reinterpret_cast<float4*>(cp) = *reinterpret_cast<float4*>(hv);
        }
        __syncthreads();
        if (chunk + 1 < 16) {
            __pipeline_wait_prior(0);
        }
    }
}

/* one pipeline stage load: A tile 128x32, B tile 32xBN.
   Bp is pre-offset to the block's column start. */
template<int BN>
__device__ __forceinline__ void load_stage(const __half* A, int lda,
                                           const __half* Bp, long ldbv,
                                           int brow, int k0,
                                           __half* As, __half* Bs, int tid) {
    const int AP  = 40;
    const int BPN = BN + 8;
    const int lr = tid >> 1;
    const int lc = (tid & 1) * 16;
    const __half* ga = A + (long)(brow + lr) * lda + k0 + lc;
    __pipeline_memcpy_async(&As[lr * AP + lc], ga, 16);
    __pipeline_memcpy_async(&As[lr * AP + lc + 8], ga + 8, 16);
    const int CH = BN / 8;
    #pragma unroll
    for (int q = 0; q < (32 * CH + 255) / 256; q++) {
        const int idx = tid + q * 256;
        if (idx < 32 * CH) {
            const int r = idx / CH;
            const int c = idx % CH;
            __pipeline_memcpy_async(&Bs[r * BPN + c * 8],
                                    Bp + (long)(k0 + r) * ldbv + c * 8, 16);
        }
    }
}

/*
 * WMMA tensor-core GEMM (NN), persistent grid-stride over tiles.
 * Block tile 128 x BN, K-step 32, 3-stage cp.async pipeline. 8 warps as
 * 4(m) x 2(n). F_FUSE: column blocks at or beyond DIMC-PART read the
 * per-batch expert weight B2/bias2 instead.
 */
template<int BN, int FLAGS>
__global__ __launch_bounds__(256, 2)
void hgemm(const __half* __restrict__ A, int lda,
           const __half* __restrict__ B, int ldb,
           float* __restrict__ Cf, __half* __restrict__ Ch, int ldc,
           int K,
           const float* __restrict__ bias,
           const float* __restrict__ res, int ldr,
           const int* __restrict__ indices, long wstride, int bstride,
           const __half* __restrict__ B2, int ldb2,
           const float* __restrict__ bias2,
           int ntx, int ntiles)
{
    constexpr int AP  = 40;
    constexpr int BPN = BN + 8;
    constexpr int ASZ = 128 * AP;
    constexpr int BSZ = 32 * BPN;

    extern __shared__ __align__(16) char dyn[];
    __half* As = reinterpret_cast<__half*>(dyn);
    __half* Bs = As + 3 * ASZ;

    const int tid  = threadIdx.x;
    const int warp = tid >> 5;
    const int lane = tid & 31;
    const int wm = warp & 3;
    const int wn = warp >> 2;
    constexpr int NTF = BN / 32;

    for (int t = blockIdx.x; t < ntiles; t += gridDim.x) {
        const int brow = (t / ntx) * 128;
        const int bcol = (t % ntx) * BN;

        const __half* Bp = B + bcol;
        const float* biasp = (FLAGS & F_BIAS) ? (bias + bcol) : bias;
        long ldbv = ldb;
        if ((FLAGS & F_FUSE) && bcol >= (DIMC - PART)) {
            const int idx = indices[brow >> 9];
            Bp    = B2 + (long)idx * wstride + (bcol - (DIMC - PART));
            biasp = bias2 + (long)idx * bstride + (bcol - (DIMC - PART));
            ldbv  = ldb2;
        }

        wmma::fragment<wmma::accumulator, 16, 16, 16, float> acc[2][NTF];
        #pragma unroll
        for (int i = 0; i < 2; i++) {
            #pragma unroll
            for (int j = 0; j < NTF; j++) wmma::fill_fragment(acc[i][j], 0.0f);
        }

        const int iters = K >> 5;

        load_stage<BN>(A, lda, Bp, ldbv, brow, 0, As, Bs, tid);
        __pipeline_commit();
        if (iters > 1) {
            load_stage<BN>(A, lda, Bp, ldbv, brow, 32, As + ASZ, Bs + BSZ, tid);
            __pipeline_commit();
        }

        for (int it = 0; it < iters; ++it) {
            if (it + 1 < iters) {
                __pipeline_wait_prior(1);
            } else {
                __pipeline_wait_prior(0);
            }
            __syncthreads();
            if (it + 2 < iters) {
                const int ns = (it + 2) % 3;
                load_stage<BN>(A, lda, Bp, ldbv, brow, (it + 2) * 32,
                               As + ns * ASZ, Bs + ns * BSZ, tid);
                __pipeline_commit();
            }
            const int slot = it % 3;

            #pragma unroll
            for (int ks = 0; ks < 32; ks += 16) {
                wmma::fragment<wmma::matrix_a, 16, 16, 16, __half, wmma::row_major> af[2];
                #pragma unroll
                for (int mt = 0; mt < 2; mt++) {
                    const __half* ap = &As[slot * ASZ + (wm * 32 + mt * 16) * AP + ks];
                    wmma::load_matrix_sync(af[mt], ap, AP);
                }
                wmma::fragment<wmma::matrix_b, 16, 16, 16, __half, wmma::row_major> bf[NTF];
                #pragma unroll
                for (int nt = 0; nt < NTF; nt++) {
                    const __half* bp = &Bs[slot * BSZ + ks * BPN + wn * (BN / 2) + nt * 16];
                    wmma::load_matrix_sync(bf[nt], bp, BPN);
                }
                #pragma unroll
                for (int mt = 0; mt < 2; mt++) {
                    #pragma unroll
                    for (int nt = 0; nt < NTF; nt++) {
                        wmma::mma_sync(acc[mt][nt], af[mt], bf[nt], acc[mt][nt]);
                    }
                }
            }
        }

        __syncthreads();

        /* epilogue: stage each 16x16 accumulator through smem */
        float* stage = reinterpret_cast<float*>(dyn) + warp * 16 * 20;
        const int er = lane >> 1;
        const int ec = (lane & 1) * 8;
        #pragma unroll
        for (int mt = 0; mt < 2; mt++) {
            #pragma unroll
            for (int nt = 0; nt < NTF; nt++) {
                wmma::store_matrix_sync(stage, acc[mt][nt], 20, wmma::mem_row_major);
                __syncwarp();
                const int row = brow + wm * 32 + mt * 16 + er;
                const int lcol = wn * (BN / 2) + nt * 16 + ec;
                const int col = bcol + lcol;
                float v[8];
                #pragma unroll
                for (int j = 0; j < 8; j++) v[j] = stage[er * 20 + ec + j];
                if (FLAGS & F_BIAS) {
                    #pragma unroll
                    for (int j = 0; j < 8; j++) v[j] += biasp[lcol + j];
                }
                if (FLAGS & F_GELU) {
                    #pragma unroll
                    for (int j = 0; j < 8; j++) v[j] = gelu_f(v[j]);
                }
                if (FLAGS & F_RES) {
                    #pragma unroll
                    for (int j = 0; j < 8; j++) v[j] += res[(long)row * ldr + col + j];
                }
                const long off = (long)row * ldc + col;
                if (FLAGS & F_OUTF) {
                    float4 f0;
                    f0.x = v[0]; f0.y = v[1]; f0.z = v[2]; f0.w = v[3];
                    float4 f1;
                    f1.x = v[4]; f1.y = v[5]; f1.z = v[6]; f1.w = v[7];
                    *reinterpret_cast<float4*>(&Cf[off]) = f0;
                    *reinterpret_cast<float4*>(&Cf[off + 4]) = f1;
                }
                if (FLAGS & F_OUTH) {
                    __half2* hp = reinterpret_cast<__half2*>(&Ch[off]);
                    hp[0] = __floats2half2_rn(v[0], v[1]);
                    hp[1] = __floats2half2_rn(v[2], v[3]);
                    hp[2] = __floats2half2_rn(v[4], v[5]);
                    hp[3] = __floats2half2_rn(v[6], v[7]);
                }
                __syncwarp();
            }
        }
        __syncthreads();
    }
}

#define SMEM_NN128 (3 * (128 * 40 + 32 * 136) * 2)
#define SMEM_ATTN  223232
#define NPERSIST   296

static inline int pgrid(int ntiles) {
    return ntiles < NPERSIST ? ntiles : NPERSIST;
}

extern "C" void kernel_launch(void* const* d_in, const int* in_sizes, int n_in,
                              void* d_out, int out_size) {
    const float* x       = (const float*)d_in[0];
    const int*   indices = (const int*)  d_in[1];
    const float* ln1_w   = (const float*)d_in[2];
    const float* ln1_b   = (const float*)d_in[3];
    const float* qkv_w   = (const float*)d_in[4];
    const float* qkv_b   = (const float*)d_in[5];
    const float* out_w   = (const float*)d_in[6];
    const float* out_b   = (const float*)d_in[7];
    const float* ln2_w   = (const float*)d_in[8];
    const float* ln2_b   = (const float*)d_in[9];
    const float* fc1_w   = (const float*)d_in[10];
    const float* fc1_b   = (const float*)d_in[11];
    const float* fc2_w   = (const float*)d_in[12];
    const float* fc2_b   = (const float*)d_in[13];
    const float* exp_w   = (const float*)d_in[14];
    const float* exp_b   = (const float*)d_in[15];

    float* out_final = (float*)d_out;
    float* attn      = out_final + (size_t)TOK * DIMC;

    void* p;
    cudaGetSymbolAddress(&p, g_xn_h);
    __half* xn_h = (__half*)p;
    cudaGetSymbolAddress(&p, g_qkv_h);
    __half* qkv_h = (__half*)p;
    cudaGetSymbolAddress(&p, g_ctx_h);
    __half* ctx_h = (__half*)p;
    cudaGetSymbolAddress(&p, g_x1);
    float* x1 = (float*)p;
    cudaGetSymbolAddress(&p, g_h_h);
    __half* h_h = (__half*)p;
    cudaGetSymbolAddress(&p, g_qkvw_h);
    __half* qkvw_h = (__half*)p;
    cudaGetSymbolAddress(&p, g_outw_h);
    __half* outw_h = (__half*)p;
    cudaGetSymbolAddress(&p, g_fc1w_h);
    __half* fc1w_h = (__half*)p;
    cudaGetSymbolAddress(&p, g_fc2w_h);
    __half* fc2w_h = (__half*)p;
    cudaGetSymbolAddress(&p, g_expw_h);
    __half* expw_h = (__half*)p;

    cudaFuncSetAttribute(hgemm<128, F_BIAS | F_OUTH>,
                         cudaFuncAttributeMaxDynamicSharedMemorySize, SMEM_NN128);
    cudaFuncSetAttribute(hgemm<128, F_BIAS | F_RES | F_OUTF>,
                         cudaFuncAttributeMaxDynamicSharedMemorySize, SMEM_NN128);
    cudaFuncSetAttribute(hgemm<128, F_BIAS | F_GELU | F_OUTH>,
                         cudaFuncAttributeMaxDynamicSharedMemorySize, SMEM_NN128);
    cudaFuncSetAttribute(hgemm<128, F_BIAS | F_RES | F_OUTF | F_FUSE>,
                         cudaFuncAttributeMaxDynamicSharedMemorySize, SMEM_NN128);
    cudaFuncSetAttribute(attn_fused_k,
                         cudaFuncAttributeMaxDynamicSharedMemorySize, SMEM_ATTN);

    const int n0 = DIMC * 3 * DIMC / 4;
    const int n1 = DIMC * DIMC / 4;
    const int n2 = DIMC * MLPC / 4;
    const int n3 = MLPC * (DIMC - PART) / 4;
    const int n4 = 8 * MLPC * PART / 4;
    const int ntot = n0 + n1 + n2 + n3 + n4;
    cvt5_k<<<(ntot + 255) / 256, 256>>>(qkv_w, qkvw_h, n0,
                                        out_w, outw_h, n1,
                                        fc1_w, fc1w_h, n2,
                                        fc2_w, fc2w_h, n3,
                                        exp_w, expw_h, n4);

    layernorm_h_k<<<TOK, 256>>>(x, ln1_w, ln1_b, xn_h);

    hgemm<128, F_BIAS | F_OUTH><<<pgrid(24 * 32), 256, SMEM_NN128>>>(
        xn_h, DIMC, qkvw_h, 3 * DIMC, nullptr, qkv_h, 3 * DIMC, DIMC,
        qkv_b, nullptr, 0, nullptr, 0, 0, nullptr, 0, nullptr,
        24, 24 * 32);

    attn_fused_k<<<dim3(128), 256, SMEM_ATTN>>>(qkv_h, attn, ctx_h);

    hgemm<128, F_BIAS | F_RES | F_OUTF><<<pgrid(8 * 32), 256, SMEM_NN128>>>(
        ctx_h, DIMC, outw_h, DIMC, x1, nullptr, DIMC, DIMC,
        out_b, x, DIMC, nullptr, 0, 0, nullptr, 0, nullptr,
        8, 8 * 32);

    layernorm_h_k<<<TOK, 256>>>(x1, ln2_w, ln2_b, xn_h);

    hgemm<128, F_BIAS | F_GELU | F_OUTH><<<pgrid(32 * 32), 256, SMEM_NN128>>>(
        xn_h, DIMC, fc1w_h, MLPC, nullptr, h_h, MLPC, DIMC,
        fc1_b, nullptr, 0, nullptr, 0, 0, nullptr, 0, nullptr,
        32, 32 * 32);

    hgemm<128, F_BIAS | F_RES | F_OUTF | F_FUSE><<<pgrid(8 * 32), 256, SMEM_NN128>>>(
        h_h, MLPC, fc2w_h, DIMC - PART, out_final, nullptr, DIMC, MLPC,
        fc2_b, x1, DIMC,
        indices, (long)MLPC * PART, PART,
        expw_h, PART, exp_b,
        8, 8 * 32);
}

// round 13
// speedup vs baseline: 1.0729x; 1.0141x over previous
#include <cuda_runtime.h>
#include <cuda_fp16.h>
#include <cuda_pipeline.h>
#include <mma.h>
#include <math.h>

#define TOK   4096
#define DIMC  1024
#define MLPC  4096
#define NSEQ  512
#define HD    64
#define PART  256

#define F_BIAS  1
#define F_GELU  2
#define F_RES   4
#define F_OUTF  16
#define F_OUTH  32
#define F_FUSE  64

using namespace nvcuda;

/* static device scratch */
__device__ __half g_xn_h [TOK * DIMC];
__device__ __half g_qkv_h[TOK * 3 * DIMC];
__device__ __half g_ctx_h[TOK * DIMC];
__device__ float  g_x1   [TOK * DIMC];
__device__ __half g_h_h  [TOK * MLPC];
__device__ __half g_qkvw_h[DIMC * 3 * DIMC];
__device__ __half g_outw_h[DIMC * DIMC];
__device__ __half g_fc1w_h[DIMC * MLPC];
__device__ __half g_fc2w_h[MLPC * (DIMC - PART)];
__device__ __half g_expw_h[8 * MLPC * PART];

__device__ __forceinline__ float gelu_f(float v) {
    return 0.5f * v * (1.0f + erff(v * 0.70710678118654752f));
}

/* fused fp32 to fp16 conversion over five weight tensors */
__global__ void cvt5_k(const float* __restrict__ w0, __half* __restrict__ o0, int n0,
                       const float* __restrict__ w1, __half* __restrict__ o1, int n1,
                       const float* __restrict__ w2, __half* __restrict__ o2, int n2,
                       const float* __restrict__ w3, __half* __restrict__ o3, int n3,
                       const float* __restrict__ w4, __half* __restrict__ o4, int n4) {
    int i = blockIdx.x * blockDim.x + threadIdx.x;
    const float* in;
    __half* out;
    if (i < n0) {
        in = w0; out = o0;
    } else if (i < n0 + n1) {
        i -= n0; in = w1; out = o1;
    } else if (i < n0 + n1 + n2) {
        i -= n0 + n1; in = w2; out = o2;
    } else if (i < n0 + n1 + n2 + n3) {
        i -= n0 + n1 + n2; in = w3; out = o3;
    } else if (i < n0 + n1 + n2 + n3 + n4) {
        i -= n0 + n1 + n2 + n3; in = w4; out = o4;
    } else {
        return;
    }
    float4 v = reinterpret_cast<const float4*>(in)[i];
    reinterpret_cast<__half2*>(out)[i * 2 + 0] = __floats2half2_rn(v.x, v.y);
    reinterpret_cast<__half2*>(out)[i * 2 + 1] = __floats2half2_rn(v.z, v.w);
}

/* layernorm fp32 in, fp16 out */
__global__ void layernorm_h_k(const float* __restrict__ x,
                              const float* __restrict__ w,
                              const float* __restrict__ b,
                              __half* __restrict__ out) {
    int row = blockIdx.x;
    int t = threadIdx.x;
    float4 v = reinterpret_cast<const float4*>(x + (size_t)row * DIMC)[t];
    float s  = v.x + v.y + v.z + v.w;
    float sq = v.x * v.x + v.y * v.y + v.z * v.z + v.w * v.w;
    #pragma unroll
    for (int o = 16; o > 0; o >>= 1) {
        s  += __shfl_down_sync(0xffffffffu, s,  o);
        sq += __shfl_down_sync(0xffffffffu, sq, o);
    }
    __shared__ float ss[8];
    __shared__ float sq2[8];
    __shared__ float mean_s;
    __shared__ float rstd_s;
    int lane = t & 31;
    int wp = t >> 5;
    if (lane == 0) { ss[wp] = s; sq2[wp] = sq; }
    __syncthreads();
    if (t == 0) {
        float S = 0.f;
        float Q = 0.f;
        #pragma unroll
        for (int i = 0; i < 8; i++) { S += ss[i]; Q += sq2[i]; }
        float m = S * (1.0f / DIMC);
        mean_s = m;
        rstd_s = rsqrtf(Q * (1.0f / DIMC) - m * m + 1e-5f);
    }
    __syncthreads();
    float m = mean_s;
    float r = rstd_s;
    float4 wv = reinterpret_cast<const float4*>(w)[t];
    float4 bv = reinterpret_cast<const float4*>(b)[t];
    float o0 = (v.x - m) * r * wv.x + bv.x;
    float o1 = (v.y - m) * r * wv.y + bv.y;
    float o2 = (v.z - m) * r * wv.z + bv.z;
    float o3 = (v.w - m) * r * wv.w + bv.w;
    __half2* op = reinterpret_cast<__half2*>(out + (size_t)row * DIMC);
    op[t * 2 + 0] = __floats2half2_rn(o0, o1);
    op[t * 2 + 1] = __floats2half2_rn(o2, o3);
}

/*
 * Persistent fused attention: one CTA per (b,h), 512 threads / 16 warps.
 * K and V live in smem for the whole kernel; loop over 16 chunks of 32
 * query rows with double-buffered Q prefetch. Per chunk:
 *   S = Q K^T      : 16 warps, each a 32x32 tile (2m x 2n frags)
 *   softmax        : 16 warps, 2 rows each (__expf), writes fp32 attn +
 *                    fp16 P aliased over the S rows
 *   P @ V          : 16 warps as 2m x 4n x 2k-halves, partials in smem
 *   ctx write      : 2-way partial sum, fp16 out
 */
__global__ __launch_bounds__(512, 1)
void attn_fused_k(const __half* __restrict__ qkv,
                  float* __restrict__ attn,
                  __half* __restrict__ ctx) {
    const int bh = blockIdx.x;
    const int b = bh >> 4;
    const int h = bh & 15;
    const int tid = threadIdx.x;
    const int warp = tid >> 5;
    const int lane = tid & 31;

    extern __shared__ __align__(16) char dyn[];
    __half* Ks = reinterpret_cast<__half*>(dyn);            /* 512 x 72 halves */
    __half* Vs = Ks + 512 * 72;                             /* 512 x 72 halves */
    float*  Ss = reinterpret_cast<float*>(Vs + 512 * 72);   /* 32 x 520 floats */
    __half* Qs = reinterpret_cast<__half*>(Ss + 32 * 520);  /* 2 x 32 x 72 halves */

    const __half* Qg = qkv + (long)b * NSEQ * 3 * DIMC + h * HD;
    const __half* Kg = Qg + DIMC;
    const __half* Vg = Qg + 2 * DIMC;

    /* load all of K, V and Q chunk 0 */
    #pragma unroll
    for (int q = 0; q < 8; q++) {
        const int idx = q * 512 + tid;
        const int row = idx >> 3;
        const int c = idx & 7;
        __pipeline_memcpy_async(&Ks[row * 72 + c * 8], Kg + (long)row * 3072 + c * 8, 16);
        __pipeline_memcpy_async(&Vs[row * 72 + c * 8], Vg + (long)row * 3072 + c * 8, 16);
    }
    if (tid < 256) {
        const int row = tid >> 3;
        const int c = tid & 7;
        __pipeline_memcpy_async(&Qs[row * 72 + c * 8], Qg + (long)row * 3072 + c * 8, 16);
    }
    __pipeline_commit();
    __pipeline_wait_prior(0);
    __syncthreads();

    for (int chunk = 0; chunk < 16; chunk++) {
        const int cur = chunk & 1;
        __half* Qc = Qs + cur * 32 * 72;

        /* prefetch next Q chunk into the other buffer */
        if (chunk + 1 < 16 && tid < 256) {
            const int row = tid >> 3;
            const int c = tid & 7;
            __pipeline_memcpy_async(&Qs[(1 - cur) * 32 * 72 + row * 72 + c * 8],
                                    Qg + (long)((chunk + 1) * 32 + row) * 3072 + c * 8, 16);
        }
        if (chunk + 1 < 16) {
            __pipeline_commit();
        }

        /* S = Q K^T : warp w covers cols [32w, 32w+32) */
        {
            wmma::fragment<wmma::accumulator, 16, 16, 16, float> sacc[2][2];
            #pragma unroll
            for (int mt = 0; mt < 2; mt++) {
                #pragma unroll
                for (int nt = 0; nt < 2; nt++) wmma::fill_fragment(sacc[mt][nt], 0.0f);
            }
            #pragma unroll
            for (int ks = 0; ks < 64; ks += 16) {
                wmma::fragment<wmma::matrix_a, 16, 16, 16, __half, wmma::row_major> af[2];
                #pragma unroll
                for (int mt = 0; mt < 2; mt++) {
                    wmma::load_matrix_sync(af[mt], &Qc[(mt * 16) * 72 + ks], 72);
                }
                wmma::fragment<wmma::matrix_b, 16, 16, 16, __half, wmma::col_major> bf[2];
                #pragma unroll
                for (int nt = 0; nt < 2; nt++) {
                    wmma::load_matrix_sync(bf[nt], &Ks[(warp * 32 + nt * 16) * 72 + ks], 72);
                }
                #pragma unroll
                for (int mt = 0; mt < 2; mt++) {
                    #pragma unroll
                    for (int nt = 0; nt < 2; nt++) {
                        wmma::mma_sync(sacc[mt][nt], af[mt], bf[nt], sacc[mt][nt]);
                    }
                }
            }
            #pragma unroll
            for (int mt = 0; mt < 2; mt++) {
                #pragma unroll
                for (int nt = 0; nt < 2; nt++) {
                    wmma::store_matrix_sync(&Ss[(mt * 16) * 520 + warp * 32 + nt * 16],
                                            sacc[mt][nt], 520, wmma::mem_row_major);
                }
            }
        }
        __syncthreads();

        /* softmax: warp w rows 2w..2w+1; write attn fp32, P fp16 aliased
           over the start of each fp32 S row (warp-private rows; the shfl
           reductions separate all reads from the aliased writes) */
        {
            float* attn_base = attn + ((long)bh * NSEQ + (long)chunk * 32) * NSEQ;
            #pragma unroll
            for (int rr = 0; rr < 2; rr++) {
                const int row = warp * 2 + rr;
                float v[16];
                float mx = -1e30f;
                #pragma unroll
                for (int j = 0; j < 16; j++) {
                    v[j] = Ss[row * 520 + lane + 32 * j] * 0.03125f;
                    mx = fmaxf(mx, v[j]);
                }
                #pragma unroll
                for (int o = 16; o > 0; o >>= 1) mx = fmaxf(mx, __shfl_xor_sync(0xffffffffu, mx, o));
                float sum = 0.f;
                #pragma unroll
                for (int j = 0; j < 16; j++) {
                    v[j] = __expf(v[j] - mx);
                    sum += v[j];
                }
                #pragma unroll
                for (int o = 16; o > 0; o >>= 1) sum += __shfl_xor_sync(0xffffffffu, sum, o);
                const float inv = 1.0f / sum;
                __half* Pr = reinterpret_cast<__half*>(Ss + (size_t)row * 520);
                #pragma unroll
                for (int j = 0; j < 16; j++) {
                    const float e = v[j] * inv;
                    attn_base[(long)row * NSEQ + lane + 32 * j] = e;
                    Pr[lane + 32 * j] = __float2half(e);
                }
            }
        }
        __syncthreads();

        /* P @ V : warp (wm, wn, kh): wm = warp&1, wn = (warp>>1)&3,
           kh = warp>>3. 16x16 output tile at rows wm*16, cols wn*16 over
           K half [kh*256, kh*256+256); partials staged in smem */
        {
            const int wm = warp & 1;
            const int wn = (warp >> 1) & 3;
            const int kh = warp >> 3;
            wmma::fragment<wmma::accumulator, 16, 16, 16, float> oacc;
            wmma::fill_fragment(oacc, 0.0f);
            const __half* Pbase = reinterpret_cast<const __half*>(Ss) + (wm * 16) * 1040;
            #pragma unroll
            for (int ks = 0; ks < 256; ks += 16) {
                const int kg = kh * 256 + ks;
                wmma::fragment<wmma::matrix_a, 16, 16, 16, __half, wmma::row_major> af;
                wmma::load_matrix_sync(af, Pbase + kg, 1040);
                wmma::fragment<wmma::matrix_b, 16, 16, 16, __half, wmma::row_major> bf;
                wmma::load_matrix_sync(bf, &Vs[kg * 72 + wn * 16], 72);
                wmma::mma_sync(oacc, af, bf, oacc);
            }
            __syncthreads();
            float* stage = Ss;
            wmma::store_matrix_sync(&stage[kh * 2048 + (wm * 16) * 64 + wn * 16],
                                    oacc, 64, wmma::mem_row_major);
        }
        __syncthreads();

        /* ctx write: sum 2 partials, fp32 -> fp16, 4 elements per thread */
        {
            const int idx = tid * 4;
            const int r = idx >> 6;
            const int c0 = idx & 63;
            float a4[4];
            #pragma unroll
            for (int j = 0; j < 4; j++) {
                a4[j] = Ss[r * 64 + c0 + j] + Ss[2048 + r * 64 + c0 + j];
            }
            __half2 hv[2];
            hv[0] = __floats2half2_rn(a4[0], a4[1]);
            hv[1] = __floats2half2_rn(a4[2], a4[3]);
            __half* cp = ctx + (long)b * NSEQ * DIMC + (long)(chunk * 32 + r) * DIMC + h * 64 + c0;
            *reinterpret_cast<float2*>(cp) = *reinterpret_cast<float2*>(hv);
        }
        __syncthreads();
        if (chunk + 1 < 16) {
            __pipeline_wait_prior(0);
        }
    }
}

/* one pipeline stage load: A tile 128x32, B tile 32xBN.
   Bp is pre-offset to the block's column start. */
template<int BN>
__device__ __forceinline__ void load_stage(const __half* A, int lda,
                                           const __half* Bp, long ldbv,
                                           int brow, int k0,
                                           __half* As, __half* Bs, int tid) {
    const int AP  = 40;
    const int BPN = BN + 8;
    const int lr = tid >> 1;
    const int lc = (tid & 1) * 16;
    const __half* ga = A + (long)(brow + lr) * lda + k0 + lc;
    __pipeline_memcpy_async(&As[lr * AP + lc], ga, 16);
    __pipeline_memcpy_async(&As[lr * AP + lc + 8], ga + 8, 16);
    const int CH = BN / 8;
    #pragma unroll
    for (int q = 0; q < (32 * CH + 255) / 256; q++) {
        const int idx = tid + q * 256;
        if (idx < 32 * CH) {
            const int r = idx / CH;
            const int c = idx % CH;
            __pipeline_memcpy_async(&Bs[r * BPN + c * 8],
                                    Bp + (long)(k0 + r) * ldbv + c * 8, 16);
        }
    }
}

/*
 * WMMA tensor-core GEMM (NN). Block tile 128 x BN, K-step 32, 3-stage
 * cp.async pipeline. 8 warps as 4(m) x 2(n). F_FUSE: column blocks at or
 * beyond DIMC-PART read the per-batch expert weight B2/bias2 instead.
 */
template<int BN, int FLAGS>
__global__ __launch_bounds__(256, 2)
void hgemm(const __half* __restrict__ A, int lda,
           const __half* __restrict__ B, int ldb,
           float* __restrict__ Cf, __half* __restrict__ Ch, int ldc,
           int K,
           const float* __restrict__ bias,
           const float* __restrict__ res, int ldr,
           const int* __restrict__ indices, long wstride, int bstride,
           const __half* __restrict__ B2, int ldb2,
           const float* __restrict__ bias2)
{
    const int brow = blockIdx.y * 128;
    const int bcol = blockIdx.x * BN;

    const __half* Bp = B + bcol;
    const float* biasp = (FLAGS & F_BIAS) ? (bias + bcol) : bias;
    long ldbv = ldb;
    if ((FLAGS & F_FUSE) && bcol >= (DIMC - PART)) {
        const int idx = indices[brow >> 9];
        Bp    = B2 + (long)idx * wstride + (bcol - (DIMC - PART));
        biasp = bias2 + (long)idx * bstride + (bcol - (DIMC - PART));
        ldbv  = ldb2;
    }

    constexpr int AP  = 40;
    constexpr int BPN = BN + 8;
    constexpr int ASZ = 128 * AP;
    constexpr int BSZ = 32 * BPN;

    extern __shared__ __align__(16) char dyn[];
    __half* As = reinterpret_cast<__half*>(dyn);
    __half* Bs = As + 3 * ASZ;

    const int tid  = threadIdx.x;
    const int warp = tid >> 5;
    const int lane = tid & 31;
    const int wm = warp & 3;
    const int wn = warp >> 2;
    constexpr int NTF = BN / 32;

    wmma::fragment<wmma::accumulator, 16, 16, 16, float> acc[2][NTF];
    #pragma unroll
    for (int i = 0; i < 2; i++) {
        #pragma unroll
        for (int j = 0; j < NTF; j++) wmma::fill_fragment(acc[i][j], 0.0f);
    }

    const int iters = K >> 5;

    load_stage<BN>(A, lda, Bp, ldbv, brow, 0, As, Bs, tid);
    __pipeline_commit();
    if (iters > 1) {
        load_stage<BN>(A, lda, Bp, ldbv, brow, 32, As + ASZ, Bs + BSZ, tid);
        __pipeline_commit();
    }

    for (int it = 0; it < iters; ++it) {
        if (it + 1 < iters) {
            __pipeline_wait_prior(1);
        } else {
            __pipeline_wait_prior(0);
        }
        __syncthreads();
        if (it + 2 < iters) {
            const int ns = (it + 2) % 3;
            load_stage<BN>(A, lda, Bp, ldbv, brow, (it + 2) * 32,
                           As + ns * ASZ, Bs + ns * BSZ, tid);
            __pipeline_commit();
        }
        const int slot = it % 3;

        #pragma unroll
        for (int ks = 0; ks < 32; ks += 16) {
            wmma::fragment<wmma::matrix_a, 16, 16, 16, __half, wmma::row_major> af[2];
            #pragma unroll
            for (int mt = 0; mt < 2; mt++) {
                const __half* ap = &As[slot * ASZ + (wm * 32 + mt * 16) * AP + ks];
                wmma::load_matrix_sync(af[mt], ap, AP);
            }
            wmma::fragment<wmma::matrix_b, 16, 16, 16, __half, wmma::row_major> bf[NTF];
            #pragma unroll
            for (int nt = 0; nt < NTF; nt++) {
                const __half* bp = &Bs[slot * BSZ + ks * BPN + wn * (BN / 2) + nt * 16];
                wmma::load_matrix_sync(bf[nt], bp, BPN);
            }
            #pragma unroll
            for (int mt = 0; mt < 2; mt++) {
                #pragma unroll
                for (int nt = 0; nt < NTF; nt++) {
                    wmma::mma_sync(acc[mt][nt], af[mt], bf[nt], acc[mt][nt]);
                }
            }
        }
    }

    __syncthreads();

    /* epilogue: stage each 16x16 accumulator through smem */
    float* stage = reinterpret_cast<float*>(dyn) + warp * 16 * 20;
    const int er = lane >> 1;
    const int ec = (lane & 1) * 8;
    #pragma unroll
    for (int mt = 0; mt < 2; mt++) {
        #pragma unroll
        for (int nt = 0; nt < NTF; nt++) {
            wmma::store_matrix_sync(stage, acc[mt][nt], 20, wmma::mem_row_major);
            __syncwarp();
            const int row = brow + wm * 32 + mt * 16 + er;
            const int lcol = wn * (BN / 2) + nt * 16 + ec;
            const int col = bcol + lcol;
            float v[8];
            #pragma unroll
            for (int j = 0; j < 8; j++) v[j] = stage[er * 20 + ec + j];
            if (FLAGS & F_BIAS) {
                #pragma unroll
                for (int j = 0; j < 8; j++) v[j] += biasp[lcol + j];
            }
            if (FLAGS & F_GELU) {
                #pragma unroll
                for (int j = 0; j < 8; j++) v[j] = gelu_f(v[j]);
            }
            if (FLAGS & F_RES) {
                #pragma unroll
                for (int j = 0; j < 8; j++) v[j] += res[(long)row * ldr + col + j];
            }
            const long off = (long)row * ldc + col;
            if (FLAGS & F_OUTF) {
                float4 f0;
                f0.x = v[0]; f0.y = v[1]; f0.z = v[2]; f0.w = v[3];
                float4 f1;
                f1.x = v[4]; f1.y = v[5]; f1.z = v[6]; f1.w = v[7];
                *reinterpret_cast<float4*>(&Cf[off]) = f0;
                *reinterpret_cast<float4*>(&Cf[off + 4]) = f1;
            }
            if (FLAGS & F_OUTH) {
                __half2* hp = reinterpret_cast<__half2*>(&Ch[off]);
                hp[0] = __floats2half2_rn(v[0], v[1]);
                hp[1] = __floats2half2_rn(v[2], v[3]);
                hp[2] = __floats2half2_rn(v[4], v[5]);
                hp[3] = __floats2half2_rn(v[6], v[7]);
            }
            __syncwarp();
        }
    }
}

#define SMEM_NN128 (3 * (128 * 40 + 32 * 136) * 2)
#define SMEM_ATTN  223232

extern "C" void kernel_launch(void* const* d_in, const int* in_sizes, int n_in,
                              void* d_out, int out_size) {
    const float* x       = (const float*)d_in[0];
    const int*   indices = (const int*)  d_in[1];
    const float* ln1_w   = (const float*)d_in[2];
    const float* ln1_b   = (const float*)d_in[3];
    const float* qkv_w   = (const float*)d_in[4];
    const float* qkv_b   = (const float*)d_in[5];
    const float* out_w   = (const float*)d_in[6];
    const float* out_b   = (const float*)d_in[7];
    const float* ln2_w   = (const float*)d_in[8];
    const float* ln2_b   = (const float*)d_in[9];
    const float* fc1_w   = (const float*)d_in[10];
    const float* fc1_b   = (const float*)d_in[11];
    const float* fc2_w   = (const float*)d_in[12];
    const float* fc2_b   = (const float*)d_in[13];
    const float* exp_w   = (const float*)d_in[14];
    const float* exp_b   = (const float*)d_in[15];

    float* out_final = (float*)d_out;
    float* attn      = out_final + (size_t)TOK * DIMC;

    void* p;
    cudaGetSymbolAddress(&p, g_xn_h);
    __half* xn_h = (__half*)p;
    cudaGetSymbolAddress(&p, g_qkv_h);
    __half* qkv_h = (__half*)p;
    cudaGetSymbolAddress(&p, g_ctx_h);
    __half* ctx_h = (__half*)p;
    cudaGetSymbolAddress(&p, g_x1);
    float* x1 = (float*)p;
    cudaGetSymbolAddress(&p, g_h_h);
    __half* h_h = (__half*)p;
    cudaGetSymbolAddress(&p, g_qkvw_h);
    __half* qkvw_h = (__half*)p;
    cudaGetSymbolAddress(&p, g_outw_h);
    __half* outw_h = (__half*)p;
    cudaGetSymbolAddress(&p, g_fc1w_h);
    __half* fc1w_h = (__half*)p;
    cudaGetSymbolAddress(&p, g_fc2w_h);
    __half* fc2w_h = (__half*)p;
    cudaGetSymbolAddress(&p, g_expw_h);
    __half* expw_h = (__half*)p;

    cudaFuncSetAttribute(hgemm<128, F_BIAS | F_OUTH>,
                         cudaFuncAttributeMaxDynamicSharedMemorySize, SMEM_NN128);
    cudaFuncSetAttribute(hgemm<128, F_BIAS | F_RES | F_OUTF>,
                         cudaFuncAttributeMaxDynamicSharedMemorySize, SMEM_NN128);
    cudaFuncSetAttribute(hgemm<128, F_BIAS | F_GELU | F_OUTH>,
                         cudaFuncAttributeMaxDynamicSharedMemorySize, SMEM_NN128);
    cudaFuncSetAttribute(hgemm<128, F_BIAS | F_RES | F_OUTF | F_FUSE>,
                         cudaFuncAttributeMaxDynamicSharedMemorySize, SMEM_NN128);
    cudaFuncSetAttribute(attn_fused_k,
                         cudaFuncAttributeMaxDynamicSharedMemorySize, SMEM_ATTN);

    const int n0 = DIMC * 3 * DIMC / 4;
    const int n1 = DIMC * DIMC / 4;
    const int n2 = DIMC * MLPC / 4;
    const int n3 = MLPC * (DIMC - PART) / 4;
    const int n4 = 8 * MLPC * PART / 4;
    const int ntot = n0 + n1 + n2 + n3 + n4;
    cvt5_k<<<(ntot + 255) / 256, 256>>>(qkv_w, qkvw_h, n0,
                                        out_w, outw_h, n1,
                                        fc1_w, fc1w_h, n2,
                                        fc2_w, fc2w_h, n3,
                                        exp_w, expw_h, n4);

    layernorm_h_k<<<TOK, 256>>>(x, ln1_w, ln1_b, xn_h);

    hgemm<128, F_BIAS | F_OUTH><<<dim3(24, 32), 256, SMEM_NN128>>>(
        xn_h, DIMC, qkvw_h, 3 * DIMC, nullptr, qkv_h, 3 * DIMC, DIMC,
        qkv_b, nullptr, 0, nullptr, 0, 0, nullptr, 0, nullptr);

    attn_fused_k<<<dim3(128), 512, SMEM_ATTN>>>(qkv_h, attn, ctx_h);

    hgemm<128, F_BIAS | F_RES | F_OUTF><<<dim3(8, 32), 256, SMEM_NN128>>>(
        ctx_h, DIMC, outw_h, DIMC, x1, nullptr, DIMC, DIMC,
        out_b, x, DIMC, nullptr, 0, 0, nullptr, 0, nullptr);

    layernorm_h_k<<<TOK, 256>>>(x1, ln2_w, ln2_b, xn_h);

    hgemm<128, F_BIAS | F_GELU | F_OUTH><<<dim3(32, 32), 256, SMEM_NN128>>>(
        xn_h, DIMC, fc1w_h, MLPC, nullptr, h_h, MLPC, DIMC,
        fc1_b, nullptr, 0, nullptr, 0, 0, nullptr, 0, nullptr);

    hgemm<128, F_BIAS | F_RES | F_OUTF | F_FUSE><<<dim3(8, 32), 256, SMEM_NN128>>>(
        h_h, MLPC, fc2w_h, DIMC - PART, out_final, nullptr, DIMC, MLPC,
        fc2_b, x1, DIMC,
        indices, (long)MLPC * PART, PART,
        expw_h, PART, exp_b);
}